// round 14
// baseline (speedup 1.0000x reference)
#include <cuda_runtime.h>
#include <cuda_fp16.h>
#include <math.h>
#include <stdint.h>

// ---------------- problem constants ----------------
#define B_   4
#define S_   2048
#define D_   1024
#define H_   256
#define E_   4
#define F_   4096
#define M_   64
#define BS_  (B_ * S_)          // 8192
#define KSP_ 204                // int(2048*0.1)

// ---------------- scratch (device globals; no allocation allowed) ----------------
// fp32 buffers
__device__ float g_scf    [(size_t)8 * S_ * S_];      // combined scores (local 0-3, sparse 4-7)
__device__ float g_memcat [(size_t)BS_ * 2 * H_];
__device__ float g_mw     [(size_t)BS_ * M_];
__device__ float g_x2     [(size_t)BS_ * D_];
__device__ float g_rw     [(size_t)BS_ * E_];
__device__ float g_eo     [(size_t)E_ * BS_ * D_];    // per-expert MoE outputs
// f16 GEMM operand buffers
__device__ __half h_xr    [(size_t)BS_ * D_];
__device__ __half h_qkv   [(size_t)2 * BS_ * 768];    // [local | sparse]
__device__ __half h_sch   [(size_t)8 * S_ * S_];      // probs (local 0-3, sparse 4-7)
__device__ __half h_vt    [(size_t)8 * H_ * S_];      // vT per batch
__device__ __half h_po    [(size_t)2 * BS_ * H_];     // attention outs [local | sparse]
__device__ __half h_hy    [(size_t)BS_ * 4 * H_];
__device__ __half h_mcr   [(size_t)BS_ * 2 * H_];
__device__ __half h_pp    [(size_t)BS_ * H_];
__device__ __half h_tt    [(size_t)BS_ * 2 * H_];
__device__ __half h_x2r   [(size_t)BS_ * D_];
__device__ __half h_hh4   [(size_t)E_ * BS_ * F_];
// f16 transposed weights [N][K]
__device__ __half h_wqkv  [(size_t)2 * 768 * 1024];   // [local | sparse]
__device__ __half h_wm    [(size_t)256 * 1024];
__device__ __half h_wo    [(size_t)256 * 512];
__device__ __half h_wi    [(size_t)256 * 1024];
__device__ __half h_wp1   [(size_t)512 * 256];
__device__ __half h_wp2   [(size_t)256 * 512];
__device__ __half h_wwb   [(size_t)1024 * 1024];
__device__ __half h_we1   [(size_t)E_ * F_ * D_];
__device__ __half h_we2   [(size_t)E_ * D_ * F_];

__device__ __forceinline__ float gelu_f(float x) {
    return 0.5f * x * (1.0f + erff(x * 0.7071067811865476f));
}
__device__ __forceinline__ void mmaf16(float* c, const uint32_t* a, const uint32_t* b) {
    asm volatile("mma.sync.aligned.m16n8k16.row.col.f32.f16.f16.f32 "
                 "{%0,%1,%2,%3}, {%4,%5,%6,%7}, {%8,%9}, {%0,%1,%2,%3};"
                 : "+f"(c[0]), "+f"(c[1]), "+f"(c[2]), "+f"(c[3])
                 : "r"(a[0]), "r"(a[1]), "r"(a[2]), "r"(a[3]), "r"(b[0]), "r"(b[1]));
}
__device__ __forceinline__ void cp16(uint32_t dst, const void* src) {
    asm volatile("cp.async.cg.shared.global [%0], [%1], 16;" :: "r"(dst), "l"(src));
}
#define CP_COMMIT asm volatile("cp.async.commit_group;" ::: "memory")
#define CP_WAIT1  asm volatile("cp.async.wait_group 1;" ::: "memory")
#define CP_WAIT0  asm volatile("cp.async.wait_group 0;" ::: "memory")
__device__ __forceinline__ uint32_t smem_u32(const void* p) {
    uint32_t a;
    asm("{ .reg .u64 t; cvta.to.shared.u64 t, %1; cvt.u32.u64 %0, t; }" : "=r"(a) : "l"(p));
    return a;
}

// ================= f16 warp-MMA GEMM (NT, K-major halves) =================
// CTA tile 128x128, 4 warps (2m x 2n), warp tile 64x64, K-chunks of 64 halves,
// 3-stage cp.async with ONE __syncthreads per chunk, m16n8k16 f16 MMA, fp32 acc.
// Per 16-k step: 32 LDS vs 32 HMMA (1:1 mix; 64x32 tile was 1.5:1).
// Row pitch = 144B = 36 words, conflict-free scalar LDS fragments.
// EPI: 0 fp32 store(+bias), 1 f16 store(+bias), 2 f16 gelu(+bias),
//      4 x2-path (C=resid+v fp32, aux1=f16 copy)
// bias indexed as bias[blockIdx.z*bias_zs + col] (per-batch bias support).
#define PITCHW 36
#define KC 64
#define STAGE_W (2 * 128 * PITCHW)
#define TC_SMEM (3 * STAGE_W * 4)             // 110592 bytes

template<int EPI>
__global__ void __launch_bounds__(128, 2)
tc_gemm_k(const __half* __restrict__ Ag, const __half* __restrict__ Bg, void* __restrict__ Cg,
          int K, int lda, int ldb, int ldc,
          long long sA, long long sB, long long sC,
          const float* __restrict__ bias, int bias_zs, float alpha,
          const float* __restrict__ resid, __half* __restrict__ aux1)
{
    extern __shared__ uint32_t sm[];
    const uint32_t smb = smem_u32(sm);
    const int tid = threadIdx.x, lane = tid & 31, wid = tid >> 5;
    const int m0 = blockIdx.y * 128, n0 = blockIdx.x * 128;
    const int wm = (wid >> 1) * 64, wn = (wid & 1) * 64;
    const int crow = tid >> 3, seg = tid & 7;   // 16 rows x 8 segs of 16B per pass

    const __half* A  = Ag + blockIdx.z * sA + (long long)(m0 + crow) * lda + seg * 8;
    const __half* Bp = Bg + blockIdx.z * sB + (long long)(n0 + crow) * ldb + seg * 8;

    const uint32_t myA = smb + (uint32_t)(crow * 144 + seg * 16);
    const uint32_t myB = myA + 128 * 144;

    float acc[4][8][4];
#pragma unroll
    for (int i = 0; i < 4; i++)
#pragma unroll
        for (int j = 0; j < 8; j++)
#pragma unroll
            for (int k = 0; k < 4; k++) acc[i][j][k] = 0.f;

    const int nch = K >> 6;

    auto issue = [&](int c) {
        const int s = c % 3;
        const uint32_t sa = myA + s * (STAGE_W * 4);
        const uint32_t sb = myB + s * (STAGE_W * 4);
        const __half* ga = A + c * KC;
        const __half* gb = Bp + c * KC;
#pragma unroll
        for (int i = 0; i < 8; i++) {
            cp16(sa + i * (16 * 144), ga + (long long)i * 16 * lda);
            cp16(sb + i * (16 * 144), gb + (long long)i * 16 * ldb);
        }
    };

    issue(0); CP_COMMIT;
    if (nch > 1) { issue(1); CP_COMMIT; }

    const int fr = lane >> 2, fq = lane & 3;
    uint32_t af[4][4], bf[8][2];

// fragment load for kstep ks (16 halves = 8 words; a: words fq, fq+4 at rows fr, fr+8)
#define LDFRAG(ks) do { \
    const int kw_ = (ks) * 8 + fq; \
    _Pragma("unroll") \
    for (int mt = 0; mt < 4; mt++) { \
        const uint32_t* p_ = Ab + (wm + mt * 16 + fr) * PITCHW + kw_; \
        af[mt][0] = p_[0]; af[mt][1] = p_[8 * PITCHW]; \
        af[mt][2] = p_[4]; af[mt][3] = p_[8 * PITCHW + 4]; \
    } \
    _Pragma("unroll") \
    for (int nt = 0; nt < 8; nt++) { \
        const uint32_t* q_ = Bb + (wn + nt * 8 + fr) * PITCHW + kw_; \
        bf[nt][0] = q_[0]; bf[nt][1] = q_[4]; \
    } \
} while (0)

#define MMASET() do { \
    _Pragma("unroll") \
    for (int mt = 0; mt < 4; mt++) \
        _Pragma("unroll") \
        for (int nt = 0; nt < 8; nt++) \
            mmaf16(acc[mt][nt], af[mt], bf[nt]); \
} while (0)

    for (int c = 0; c < nch; c++) {
        if (c + 1 < nch) { CP_WAIT1; } else { CP_WAIT0; }
        __syncthreads();
        // safe: buffer (c+2)%3 was last read at iter c-1; all threads passed the
        // barrier above after finishing that read.
        if (c + 2 < nch) { issue(c + 2); CP_COMMIT; }

        const uint32_t* Ab = sm + (c % 3) * STAGE_W;
        const uint32_t* Bb = Ab + 128 * PITCHW;

        LDFRAG(0); MMASET();
        LDFRAG(1); MMASET();
        LDFRAG(2); MMASET();
        LDFRAG(3); MMASET();
    }
#undef LDFRAG
#undef MMASET

    // ---- epilogue ----
    const int cq = (lane & 3) * 2;
    const float* bz = bias ? (bias + (long long)blockIdx.z * bias_zs) : nullptr;
#pragma unroll
    for (int mt = 0; mt < 4; mt++) {
        int gr0 = m0 + wm + mt * 16 + fr;
        int gr1 = gr0 + 8;
#pragma unroll
        for (int nt = 0; nt < 8; nt++) {
            int gc = n0 + wn + nt * 8 + cq;
            float b0 = bz ? bz[gc] : 0.f;
            float b1 = bz ? bz[gc + 1] : 0.f;
            float v00 = acc[mt][nt][0] * alpha + b0;
            float v01 = acc[mt][nt][1] * alpha + b1;
            float v10 = acc[mt][nt][2] * alpha + b0;
            float v11 = acc[mt][nt][3] * alpha + b1;
            long long o0 = (long long)gr0 * ldc + gc;
            long long o1 = (long long)gr1 * ldc + gc;
            if (EPI == 2) {
                v00 = gelu_f(v00); v01 = gelu_f(v01);
                v10 = gelu_f(v10); v11 = gelu_f(v11);
            }
            if (EPI == 0) {
                float* C = (float*)Cg + blockIdx.z * sC;
                *(float2*)(C + o0) = make_float2(v00, v01);
                *(float2*)(C + o1) = make_float2(v10, v11);
            } else if (EPI == 1 || EPI == 2) {
                __half* C = (__half*)Cg + blockIdx.z * sC;
                *(__half2*)(C + o0) = __floats2half2_rn(v00, v01);
                *(__half2*)(C + o1) = __floats2half2_rn(v10, v11);
            } else { // EPI 4: x2 = resid + v (fp32); aux1 = f16(x2)
                float* C = (float*)Cg;
                float w00 = resid[o0] + v00, w01 = resid[o0 + 1] + v01;
                float w10 = resid[o1] + v10, w11 = resid[o1 + 1] + v11;
                *(float2*)(C + o0) = make_float2(w00, w01);
                *(float2*)(C + o1) = make_float2(w10, w11);
                *(__half2*)(aux1 + o0) = __floats2half2_rn(w00, w01);
                *(__half2*)(aux1 + o1) = __floats2half2_rn(w10, w11);
            }
        }
    }
}

static void tcg(int epi,
                const __half* A, const __half* Bm, void* C,
                int M, int N, int K, int lda, int ldb, int ldc,
                long long sA, long long sB, long long sC, int batch,
                const float* bias, int bias_zs, float alpha,
                const float* resid = nullptr, __half* aux1 = nullptr)
{
    dim3 g(N / 128, M / 128, batch), blk(128);
#define LNCH(EP) do { \
    cudaFuncSetAttribute(tc_gemm_k<EP>, cudaFuncAttributeMaxDynamicSharedMemorySize, TC_SMEM); \
    tc_gemm_k<EP><<<g, blk, TC_SMEM>>>(A, Bm, C, K, lda, ldb, ldc, sA, sB, sC, bias, bias_zs, alpha, resid, aux1); \
} while (0)
    if (epi == 0) LNCH(0);
    else if (epi == 1) LNCH(1);
    else if (epi == 2) LNCH(2);
    else LNCH(4);
#undef LNCH
}

// ================= weight transpose + f16 convert =================
__global__ void roundTh_k(const float* __restrict__ in, __half* __restrict__ out,
                          int K, int N, long long inS, long long outS)
{
    __shared__ float t[32][33];
    const float* ip = in + blockIdx.z * inS;
    __half* op = out + blockIdx.z * outS;
    int n0 = blockIdx.x * 32, k0 = blockIdx.y * 32;
    int tx = threadIdx.x & 31, ty = threadIdx.x >> 5;
#pragma unroll
    for (int i = 0; i < 32; i += 8)
        t[ty + i][tx] = ip[(long long)(k0 + ty + i) * N + n0 + tx];
    __syncthreads();
#pragma unroll
    for (int i = 0; i < 32; i += 8)
        op[(long long)(n0 + ty + i) * K + k0 + tx] = __float2half_rn(t[tx][ty + i]);
}

__global__ void cvtH_k(const float* __restrict__ a, __half* __restrict__ b, int n) {
    int i = blockIdx.x * 256 + threadIdx.x;
    if (i < n) b[i] = __float2half_rn(a[i]);
}

// v transpose: qkv f16 [8 batches of S][768] cols 512.. -> vT f16 [8][H][S]
__global__ void vtrans_k(const __half* __restrict__ qkv, __half* __restrict__ vT) {
    __shared__ __half t[32][34];
    int s0 = blockIdx.x * 32, h0 = blockIdx.y * 32, z = blockIdx.z;
    int tx = threadIdx.x & 31, ty = threadIdx.x >> 5;
#pragma unroll
    for (int i = 0; i < 32; i += 8)
        t[ty + i][tx] = qkv[(long long)(z * S_ + s0 + ty + i) * 768 + 512 + h0 + tx];
    __syncthreads();
#pragma unroll
    for (int i = 0; i < 32; i += 8)
        vT[(long long)z * H_ * S_ + (long long)(h0 + ty + i) * S_ + s0 + tx] = t[tx][ty + i];
}

// pack attention outs: po [2][BS][H] f16 -> hy [BS][4H] cols [0:2H)
__global__ void pack_po_k(const __half* __restrict__ po, __half* __restrict__ hy) {
    int i = blockIdx.x * 256 + threadIdx.x;           // i over BS*H/8 per source
    const int per = BS_ * H_ / 8;
    int src = i / per;                                 // 0 local, 1 sparse
    int j = i % per;
    int t = j / (H_ / 8), h8 = j % (H_ / 8);
    uint4 v = *(const uint4*)(po + (long long)src * BS_ * H_ + (long long)t * H_ + h8 * 8);
    *(uint4*)(hy + (long long)t * 4 * H_ + src * H_ + h8 * 8) = v;
}

// MoE fuse: out = x2 + sum_e rw[t][e] * (eo[e][t][d] + be2[e][d])
__global__ void moe_fuse_k(const float* __restrict__ x2, const float* __restrict__ eo,
                           const float* __restrict__ rw, const float* __restrict__ be2,
                           float* __restrict__ out) {
    int i = blockIdx.x * 256 + threadIdx.x;           // i over BS*D/4
    if (i >= BS_ * D_ / 4) return;
    int t = (i * 4) / D_, d = (i * 4) % D_;
    float4 r = *(const float4*)(x2 + (long long)i * 4);
    const float* rwt = rw + (long long)t * 4;
#pragma unroll
    for (int e = 0; e < E_; e++) {
        float w = rwt[e];
        float4 v = *(const float4*)(eo + (long long)e * BS_ * D_ + (long long)t * D_ + d);
        float4 b = *(const float4*)(be2 + (long long)e * D_ + d);
        r.x += w * (v.x + b.x); r.y += w * (v.y + b.y);
        r.z += w * (v.z + b.z); r.w += w * (v.w + b.w);
    }
    *(float4*)(out + (long long)i * 4) = r;
}

// ================= fallback SIMT GEMM (small fp32 shapes) =================
template<bool TRANSB>
__global__ __launch_bounds__(256, 2)
void gemm_k(const float* __restrict__ Ag, const float* __restrict__ Bg,
            float* __restrict__ Cg,
            int M, int N, int K, int lda, int ldb, int ldc)
{
    __shared__ float As[8][128];
    __shared__ float Bs[8][128];
    const float* A = Ag;
    const float* Bm = Bg;
    float* C = Cg;
    const int m0 = blockIdx.y * 128, n0 = blockIdx.x * 128;
    const int tid = threadIdx.x;
    const int tx = tid & 15, ty = tid >> 4;

    float acc[8][8];
#pragma unroll
    for (int i = 0; i < 8; i++)
#pragma unroll
        for (int j = 0; j < 8; j++) acc[i][j] = 0.f;

    const int am = tid >> 1, ak = (tid & 1) << 2;

    for (int k0 = 0; k0 < K; k0 += 8) {
        float4 av = *(const float4*)(A + (long long)(m0 + am) * lda + k0 + ak);
        As[ak + 0][am] = av.x; As[ak + 1][am] = av.y;
        As[ak + 2][am] = av.z; As[ak + 3][am] = av.w;
        if (!TRANSB) {
            int bk = tid >> 5, bn = (tid & 31) << 2;
            float4 bv = make_float4(0.f, 0.f, 0.f, 0.f);
            if (n0 + bn < N)
                bv = *(const float4*)(Bm + (long long)(k0 + bk) * ldb + n0 + bn);
            *(float4*)&Bs[bk][bn] = bv;
        } else {
            int bn = tid >> 1, bk = (tid & 1) << 2;
            float4 bv = make_float4(0.f, 0.f, 0.f, 0.f);
            if (n0 + bn < N)
                bv = *(const float4*)(Bm + (long long)(n0 + bn) * ldb + k0 + bk);
            Bs[bk + 0][bn] = bv.x; Bs[bk + 1][bn] = bv.y;
            Bs[bk + 2][bn] = bv.z; Bs[bk + 3][bn] = bv.w;
        }
        __syncthreads();
#pragma unroll
        for (int k = 0; k < 8; k++) {
            float4 a0 = *(float4*)&As[k][ty * 4];
            float4 a1 = *(float4*)&As[k][ty * 4 + 64];
            float4 b0 = *(float4*)&Bs[k][tx * 4];
            float4 b1 = *(float4*)&Bs[k][tx * 4 + 64];
            float a[8] = {a0.x, a0.y, a0.z, a0.w, a1.x, a1.y, a1.z, a1.w};
            float b[8] = {b0.x, b0.y, b0.z, b0.w, b1.x, b1.y, b1.z, b1.w};
#pragma unroll
            for (int i = 0; i < 8; i++)
#pragma unroll
                for (int j = 0; j < 8; j++) acc[i][j] += a[i] * b[j];
        }
        __syncthreads();
    }

#pragma unroll
    for (int i = 0; i < 8; i++) {
        int gr = m0 + ty * 4 + (i & 3) + ((i >> 2) << 6);
        float* Crow = C + (long long)gr * ldc;
#pragma unroll
        for (int j = 0; j < 8; j++) {
            int gc = n0 + tx * 4 + (j & 3) + ((j >> 2) << 6);
            if (gc < N) Crow[gc] = acc[i][j];
        }
    }
}

// ---------------- softmax over full rows of 2048: float in, f16 probs out ----------------
__global__ void softmax2048_k(const float* __restrict__ Sc, __half* __restrict__ P) {
    __shared__ float red[256];
    const int tid = threadIdx.x;
    const float* p = Sc + (long long)blockIdx.x * 2048;
    __half* q = P + (long long)blockIdx.x * 2048;
    float v[8];
    float mx = -3.4e38f;
#pragma unroll
    for (int i = 0; i < 8; i++) { v[i] = p[tid + i * 256]; mx = fmaxf(mx, v[i]); }
    red[tid] = mx; __syncthreads();
    for (int s = 128; s; s >>= 1) { if (tid < s) red[tid] = fmaxf(red[tid], red[tid + s]); __syncthreads(); }
    mx = red[0]; __syncthreads();
    float sum = 0.f;
#pragma unroll
    for (int i = 0; i < 8; i++) { v[i] = expf(v[i] - mx); sum += v[i]; }
    red[tid] = sum; __syncthreads();
    for (int s = 128; s; s >>= 1) { if (tid < s) red[tid] += red[tid + s]; __syncthreads(); }
    float inv = 1.f / red[0];
#pragma unroll
    for (int i = 0; i < 8; i++) q[tid + i * 256] = __float2half_rn(v[i] * inv);
}

// ---------------- sparse top-k via exact radix select + masked softmax (f16 probs out) ----------------
__global__ void sparse_softmax_k(const float* __restrict__ Sc, __half* __restrict__ P) {
    __shared__ uint32_t hist[256];
    __shared__ uint32_t sfx[257];
    __shared__ uint32_t s_prefix, s_k;
    __shared__ float red[256];
    const int tid = threadIdx.x;
    const float* p = Sc + (long long)blockIdx.x * 2048;
    __half* q = P + (long long)blockIdx.x * 2048;

    float v[8]; uint32_t key[8];
    float mx = -3.4e38f;
#pragma unroll
    for (int i = 0; i < 8; i++) {
        v[i] = p[tid + i * 256];
        mx = fmaxf(mx, v[i]);
        uint32_t u = __float_as_uint(v[i]);
        key[i] = (u & 0x80000000u) ? ~u : (u | 0x80000000u);
    }
    red[tid] = mx; __syncthreads();
    for (int s = 128; s; s >>= 1) { if (tid < s) red[tid] = fmaxf(red[tid], red[tid + s]); __syncthreads(); }
    mx = red[0];

    uint32_t prefix = 0, kk = KSP_;
#pragma unroll 1
    for (int b = 3; b >= 0; b--) {
        const int sh = b * 8;
        const uint32_t pmask = (b == 3) ? 0u : ~((1u << (sh + 8)) - 1u);
        hist[tid] = 0;
        if (tid == 0) sfx[256] = 0;
        __syncthreads();
#pragma unroll
        for (int i = 0; i < 8; i++)
            if ((key[i] & pmask) == prefix)
                atomicAdd(&hist[(key[i] >> sh) & 255u], 1u);
        __syncthreads();
        sfx[tid] = hist[tid];
        __syncthreads();
        for (int off = 1; off < 256; off <<= 1) {
            uint32_t add = (tid + off < 256) ? sfx[tid + off] : 0u;
            __syncthreads();
            sfx[tid] += add;
            __syncthreads();
        }
        if (sfx[tid] >= kk && (tid == 255 || sfx[tid + 1] < kk)) {
            s_prefix = prefix | ((uint32_t)tid << sh);
            s_k = kk - sfx[tid + 1];
        }
        __syncthreads();
        prefix = s_prefix; kk = s_k;
        __syncthreads();
    }
    const uint32_t tk = prefix;
    const float thr = (tk & 0x80000000u) ? __uint_as_float(tk ^ 0x80000000u)
                                         : __uint_as_float(~tk);

    float e[8]; float sum = 0.f;
#pragma unroll
    for (int i = 0; i < 8; i++) {
        float ev = (v[i] >= thr) ? expf(v[i] - mx) : 0.f;
        e[i] = ev; sum += ev;
    }
    red[tid] = sum; __syncthreads();
    for (int s = 128; s; s >>= 1) { if (tid < s) red[tid] += red[tid + s]; __syncthreads(); }
    float inv = 1.f / red[0];
#pragma unroll
    for (int i = 0; i < 8; i++) q[tid + i * 256] = __float2half_rn(e[i] * inv);
}

// ---------------- softmax rows of 64 ----------------
__global__ void softmax64_k(float* __restrict__ mw, int rows) {
    int row = (blockIdx.x * blockDim.x + threadIdx.x) >> 5;
    int lane = threadIdx.x & 31;
    if (row >= rows) return;
    float* p = mw + (long long)row * 64;
    float a = p[lane], b = p[lane + 32];
    float mx = fmaxf(a, b);
    for (int o = 16; o; o >>= 1) mx = fmaxf(mx, __shfl_xor_sync(0xffffffffu, mx, o));
    float ea = expf(a - mx), eb = expf(b - mx);
    float s = ea + eb;
    for (int o = 16; o; o >>= 1) s += __shfl_xor_sync(0xffffffffu, s, o);
    float inv = 1.f / s;
    p[lane] = ea * inv; p[lane + 32] = eb * inv;
}

// ---------------- router ----------------
__global__ void router_k(const float* __restrict__ x2, const float* __restrict__ Wr,
                         const float* __restrict__ br, float* __restrict__ rw, int rows) {
    int tok = (blockIdx.x * blockDim.x + threadIdx.x) >> 5;
    int lane = threadIdx.x & 31;
    if (tok >= rows) return;
    const float* xr = x2 + (long long)tok * D_;
    float s0 = 0.f, s1 = 0.f, s2 = 0.f, s3 = 0.f;
    for (int d = lane; d < D_; d += 32) {
        float xv = xr[d];
        const float* w = Wr + d * 4;
        s0 += xv * w[0]; s1 += xv * w[1]; s2 += xv * w[2]; s3 += xv * w[3];
    }
    for (int o = 16; o; o >>= 1) {
        s0 += __shfl_xor_sync(0xffffffffu, s0, o);
        s1 += __shfl_xor_sync(0xffffffffu, s1, o);
        s2 += __shfl_xor_sync(0xffffffffu, s2, o);
        s3 += __shfl_xor_sync(0xffffffffu, s3, o);
    }
    if (lane == 0) {
        s0 += br[0]; s1 += br[1]; s2 += br[2]; s3 += br[3];
        float mx = fmaxf(fmaxf(s0, s1), fmaxf(s2, s3));
        float e0 = expf(s0 - mx), e1 = expf(s1 - mx), e2 = expf(s2 - mx), e3 = expf(s3 - mx);
        float inv = 1.f / (e0 + e1 + e2 + e3);
        float* o4 = rw + (long long)tok * 4;
        o4[0] = e0 * inv; o4[1] = e1 * inv; o4[2] = e2 * inv; o4[3] = e3 * inv;
    }
}

// ---------------- launch ----------------
extern "C" void kernel_launch(void* const* d_in, const int* in_sizes, int n_in,
                              void* d_out, int out_size) {
    const float* x     = (const float*)d_in[0];
    const float* WqkvL = (const float*)d_in[1];
    const float* WqkvS = (const float*)d_in[2];
    const float* memb  = (const float*)d_in[3];
    const float* Wm    = (const float*)d_in[4];
    const float* Wo    = (const float*)d_in[5];
    const float* bo    = (const float*)d_in[6];
    const float* Wi    = (const float*)d_in[7];
    const float* bi    = (const float*)d_in[8];
    const float* Wp1   = (const float*)d_in[9];
    const float* bp1   = (const float*)d_in[10];
    const float* Wp2   = (const float*)d_in[11];
    const float* bp2   = (const float*)d_in[12];
    const float* Wwb   = (const float*)d_in[13];
    const float* bwb   = (const float*)d_in[14];
    const float* Wr    = (const float*)d_in[15];
    const float* br    = (const float*)d_in[16];
    const float* We1   = (const float*)d_in[17];
    const float* be1   = (const float*)d_in[18];
    const float* We2   = (const float*)d_in[19];
    const float* be2   = (const float*)d_in[20];
    float* out = (float*)d_out;

    float *scf, *mc, *mw, *x2, *rw, *eo;
    __half *xr, *qkv, *sch, *vt, *po, *hy, *mcr, *pp, *tt, *x2r, *hh4;
    __half *wqkv, *wm, *wo, *wi, *wp1, *wp2, *wwb, *we1, *we2;
    cudaGetSymbolAddress((void**)&scf, g_scf);
    cudaGetSymbolAddress((void**)&mc,  g_memcat);
    cudaGetSymbolAddress((void**)&mw,  g_mw);
    cudaGetSymbolAddress((void**)&x2,  g_x2);
    cudaGetSymbolAddress((void**)&rw,  g_rw);
    cudaGetSymbolAddress((void**)&eo,  g_eo);
    cudaGetSymbolAddress((void**)&xr,  h_xr);
    cudaGetSymbolAddress((void**)&qkv, h_qkv);
    cudaGetSymbolAddress((void**)&sch, h_sch);
    cudaGetSymbolAddress((void**)&vt,  h_vt);
    cudaGetSymbolAddress((void**)&po,  h_po);
    cudaGetSymbolAddress((void**)&hy,  h_hy);
    cudaGetSymbolAddress((void**)&mcr, h_mcr);
    cudaGetSymbolAddress((void**)&pp,  h_pp);
    cudaGetSymbolAddress((void**)&tt,  h_tt);
    cudaGetSymbolAddress((void**)&x2r, h_x2r);
    cudaGetSymbolAddress((void**)&hh4, h_hh4);
    cudaGetSymbolAddress((void**)&wqkv, h_wqkv);
    cudaGetSymbolAddress((void**)&wm,  h_wm);
    cudaGetSymbolAddress((void**)&wo,  h_wo);
    cudaGetSymbolAddress((void**)&wi,  h_wi);
    cudaGetSymbolAddress((void**)&wp1, h_wp1);
    cudaGetSymbolAddress((void**)&wp2, h_wp2);
    cudaGetSymbolAddress((void**)&wwb, h_wwb);
    cudaGetSymbolAddress((void**)&we1, h_we1);
    cudaGetSymbolAddress((void**)&we2, h_we2);

    const float scale = 0.0625f; // H^-0.5
    dim3 t256(256);

    // ---- pre-pass + attention (launch #6 = batch-8 score GEMM for ncu) ----
    roundTh_k<<<dim3(768 / 32, 1024 / 32, 1), t256>>>(WqkvL, wqkv, 1024, 768, 0, 0);                 // 1
    roundTh_k<<<dim3(768 / 32, 1024 / 32, 1), t256>>>(WqkvS, wqkv + (size_t)768 * 1024, 1024, 768, 0, 0); // 2
    cvtH_k<<<(BS_ * D_ + 255) / 256, 256>>>(x, xr, BS_ * D_);                                        // 3
    // QKV batch=2 (same A, two weight sets, outputs contiguous)
    tcg(1, xr, wqkv, qkv, BS_, 768, D_, D_, D_, 768,
        0, (long long)768 * 1024, (long long)BS_ * 768, 2, nullptr, 0, 1.f);                         // 4
    vtrans_k<<<dim3(S_ / 32, H_ / 32, 8), t256>>>(qkv, vt);                                          // 5
    // scores batch=8 (local batches 0-3, sparse 4-7; qkv z-stride = S*768)
    tcg(0, qkv, qkv + H_, scf, S_, S_, H_, 768, 768, S_,
        (long long)S_ * 768, (long long)S_ * 768, (long long)S_ * S_, 8, nullptr, 0, scale);         // 6 <- profiled
    softmax2048_k<<<BS_, 256>>>(scf, sch);
    sparse_softmax_k<<<BS_, 256>>>(scf + (size_t)4 * S_ * S_, sch + (size_t)4 * S_ * S_);
    // PV batch=8
    tcg(1, sch, vt, po, S_, H_, S_, S_, S_, H_,
        (long long)S_ * S_, (long long)H_ * S_, (long long)S_ * H_, 8, nullptr, 0, 1.f);
    pack_po_k<<<(2 * BS_ * H_ / 8 + 255) / 256, 256>>>(po, hy);

    // ---- memory branch ----
    roundTh_k<<<dim3(256 / 32, 1024 / 32, 1), t256>>>(Wm, wm, 1024, 256, 0, 0);
    roundTh_k<<<dim3(256 / 32, 512 / 32, 1), t256>>>(Wo, wo, 512, 256, 0, 0);
    tcg(0, xr, wm, mc, BS_, H_, D_, D_, D_, 2 * H_, 0, 0, 0, 1, nullptr, 0, 1.f);
    gemm_k<true><<<dim3(1, BS_ / 128, 1), t256>>>(mc, memb, mw, BS_, M_, H_, 2 * H_, H_, M_);
    softmax64_k<<<(BS_ * 32 + 255) / 256, 256>>>(mw, BS_);
    gemm_k<false><<<dim3(2, BS_ / 128, 1), t256>>>(mw, memb, mc + H_, BS_, H_, M_, M_, H_, 2 * H_);
    cvtH_k<<<(BS_ * 2 * H_ + 255) / 256, 256>>>(mc, mcr, BS_ * 2 * H_);
    tcg(1, mcr, wo, hy + 2 * H_, BS_, H_, 2 * H_, 2 * H_, 2 * H_, 4 * H_, 0, 0, 0, 1, bo, 0, 1.f);

    // ---- predictor branch ----
    roundTh_k<<<dim3(256 / 32, 1024 / 32, 1), t256>>>(Wi, wi, 1024, 256, 0, 0);
    roundTh_k<<<dim3(512 / 32, 256 / 32, 1), t256>>>(Wp1, wp1, 256, 512, 0, 0);
    roundTh_k<<<dim3(256 / 32, 512 / 32, 1), t256>>>(Wp2, wp2, 512, 256, 0, 0);
    roundTh_k<<<dim3(1024 / 32, 1024 / 32, 1), t256>>>(Wwb, wwb, 1024, 1024, 0, 0);
    tcg(1, xr, wi, pp, BS_, H_, D_, D_, D_, H_, 0, 0, 0, 1, bi, 0, 1.f);
    tcg(2, pp, wp1, tt, BS_, 2 * H_, H_, H_, H_, 2 * H_, 0, 0, 0, 1, bp1, 0, 1.f);
    tcg(1, tt, wp2, hy + 3 * H_, BS_, H_, 2 * H_, 2 * H_, 2 * H_, 4 * H_, 0, 0, 0, 1, bp2, 0, 1.f);

    // ---- hydra combine (fused: x2 = x + concat@Wwb + bwb; x2r = f16(x2)) ----
    tcg(4, hy, wwb, x2, BS_, D_, 4 * H_, 4 * H_, 4 * H_, D_, 0, 0, 0, 1, bwb, 0, 1.f, x, x2r);

    // ---- router + MoE (batched) ----
    router_k<<<(BS_ * 32 + 255) / 256, 256>>>(x2, Wr, br, rw, BS_);
    roundTh_k<<<dim3(F_ / 32, D_ / 32, E_), t256>>>(We1, we1, D_, F_, (long long)D_ * F_, (long long)F_ * D_);
    roundTh_k<<<dim3(D_ / 32, F_ / 32, E_), t256>>>(We2, we2, F_, D_, (long long)F_ * D_, (long long)D_ * F_);
    // GEMM1 batch=4: h = gelu(x2 @ We1_e + be1_e)
    tcg(2, x2r, we1, hh4, BS_, F_, D_, D_, D_, F_,
        0, (long long)F_ * D_, (long long)BS_ * F_, 4, be1, F_, 1.f);
    // GEMM2 batch=4: eo_e = h_e @ We2_e  (bias folded into fuse)
    tcg(0, hh4, we2, eo, BS_, D_, F_, F_, F_, D_,
        (long long)BS_ * F_, (long long)D_ * F_, (long long)BS_ * D_, 4, nullptr, 0, 1.f);
    // out = x2 + sum_e rw_e * (eo_e + be2_e)
    moe_fuse_k<<<(BS_ * D_ / 4 + 255) / 256, 256>>>(x2, eo, rw, be2, out);
}

// round 15
// speedup vs baseline: 1.0506x; 1.0506x over previous
#include <cuda_runtime.h>
#include <cuda_fp16.h>
#include <math.h>
#include <stdint.h>

// ---------------- problem constants ----------------
#define B_   4
#define S_   2048
#define D_   1024
#define H_   256
#define E_   4
#define F_   4096
#define M_   64
#define BS_  (B_ * S_)          // 8192
#define KSP_ 204                // int(2048*0.1)

// ---------------- scratch (device globals; no allocation allowed) ----------------
// fp32 buffers
__device__ float g_scf    [(size_t)8 * S_ * S_];      // combined scores (local 0-3, sparse 4-7)
__device__ float g_mwp    [(size_t)BS_ * 128];        // mem scores (padded to 128 cols)
__device__ float g_x2     [(size_t)BS_ * D_];
__device__ float g_rw     [(size_t)BS_ * E_];
__device__ float g_eo     [(size_t)E_ * BS_ * D_];    // per-expert MoE outputs
// f16 GEMM operand buffers
__device__ __half h_xr    [(size_t)BS_ * D_];
__device__ __half h_qkv   [(size_t)2 * BS_ * 768];    // [local | sparse]
__device__ __half h_sch   [(size_t)8 * S_ * S_];      // probs (local 0-3, sparse 4-7)
__device__ __half h_vt    [(size_t)8 * H_ * S_];      // vT per batch
__device__ __half h_po    [(size_t)2 * BS_ * H_];     // attention outs [local | sparse]
__device__ __half h_hy    [(size_t)BS_ * 4 * H_];
__device__ __half h_mcr   [(size_t)BS_ * 2 * H_];     // [xp | retrieved] f16
__device__ __half h_mwh   [(size_t)BS_ * M_];         // mem softmax weights f16
__device__ __half h_membp [(size_t)128 * H_];         // memb padded [128][256]
__device__ __half h_membT [(size_t)H_ * M_];          // memb^T [256][64]
__device__ __half h_pp    [(size_t)BS_ * H_];
__device__ __half h_tt    [(size_t)BS_ * 2 * H_];
__device__ __half h_x2r   [(size_t)BS_ * D_];
__device__ __half h_hh4   [(size_t)E_ * BS_ * F_];
// f16 transposed weights [N][K]
__device__ __half h_wqkv  [(size_t)2 * 768 * 1024];   // [local | sparse]
__device__ __half h_wm    [(size_t)256 * 1024];
__device__ __half h_wo    [(size_t)256 * 512];
__device__ __half h_wi    [(size_t)256 * 1024];
__device__ __half h_wp1   [(size_t)512 * 256];
__device__ __half h_wp2   [(size_t)256 * 512];
__device__ __half h_wwb   [(size_t)1024 * 1024];
__device__ __half h_we1   [(size_t)E_ * F_ * D_];
__device__ __half h_we2   [(size_t)E_ * D_ * F_];

__device__ __forceinline__ float gelu_f(float x) {
    return 0.5f * x * (1.0f + erff(x * 0.7071067811865476f));
}
__device__ __forceinline__ void mmaf16(float* c, const uint32_t* a, const uint32_t* b) {
    asm volatile("mma.sync.aligned.m16n8k16.row.col.f32.f16.f16.f32 "
                 "{%0,%1,%2,%3}, {%4,%5,%6,%7}, {%8,%9}, {%0,%1,%2,%3};"
                 : "+f"(c[0]), "+f"(c[1]), "+f"(c[2]), "+f"(c[3])
                 : "r"(a[0]), "r"(a[1]), "r"(a[2]), "r"(a[3]), "r"(b[0]), "r"(b[1]));
}
__device__ __forceinline__ void cp16(uint32_t dst, const void* src) {
    asm volatile("cp.async.cg.shared.global [%0], [%1], 16;" :: "r"(dst), "l"(src));
}
#define CP_COMMIT asm volatile("cp.async.commit_group;" ::: "memory")
#define CP_WAIT1  asm volatile("cp.async.wait_group 1;" ::: "memory")
#define CP_WAIT0  asm volatile("cp.async.wait_group 0;" ::: "memory")
__device__ __forceinline__ uint32_t smem_u32(const void* p) {
    uint32_t a;
    asm("{ .reg .u64 t; cvta.to.shared.u64 t, %1; cvt.u32.u64 %0, t; }" : "=r"(a) : "l"(p));
    return a;
}

// ================= f16 warp-MMA GEMM (NT, K-major halves) =================
// R13 config (best known): CTA 128x128, 8 warps (2m x 4n), warp tile 64x32,
// K-chunks of 64 halves, 3-stage cp.async, ONE __syncthreads per chunk.
// Row pitch = 144B = 36 words, conflict-free scalar LDS fragments.
// EPI: 0 fp32 store(+bias), 1 f16 store(+bias), 2 f16 gelu(+bias),
//      4 x2-path (C=resid+v fp32, aux1=f16 copy)
#define PITCHW 36
#define KC 64
#define STAGE_W (2 * 128 * PITCHW)
#define TC_SMEM (3 * STAGE_W * 4)             // 110592 bytes

template<int EPI>
__global__ void __launch_bounds__(256, 2)
tc_gemm_k(const __half* __restrict__ Ag, const __half* __restrict__ Bg, void* __restrict__ Cg,
          int K, int lda, int ldb, int ldc,
          long long sA, long long sB, long long sC,
          const float* __restrict__ bias, int bias_zs, float alpha,
          const float* __restrict__ resid, __half* __restrict__ aux1)
{
    extern __shared__ uint32_t sm[];
    const uint32_t smb = smem_u32(sm);
    const int tid = threadIdx.x, lane = tid & 31, wid = tid >> 5;
    const int m0 = blockIdx.y * 128, n0 = blockIdx.x * 128;
    const int wm = (wid >> 2) * 64, wn = (wid & 3) * 32;
    const int crow = tid >> 3, seg = tid & 7;

    const __half* A  = Ag + blockIdx.z * sA + (long long)(m0 + crow) * lda + seg * 8;
    const __half* Bp = Bg + blockIdx.z * sB + (long long)(n0 + crow) * ldb + seg * 8;

    const uint32_t myA = smb + (uint32_t)(crow * 144 + seg * 16);
    const uint32_t myB = myA + 128 * 144;

    float acc[4][4][4];
#pragma unroll
    for (int i = 0; i < 4; i++)
#pragma unroll
        for (int j = 0; j < 4; j++)
#pragma unroll
            for (int k = 0; k < 4; k++) acc[i][j][k] = 0.f;

    const int nch = K >> 6;

    auto issue = [&](int c) {
        const int s = c % 3;
        const uint32_t sa = myA + s * (STAGE_W * 4);
        const uint32_t sb = myB + s * (STAGE_W * 4);
        const __half* ga = A + c * KC;
        const __half* gb = Bp + c * KC;
#pragma unroll
        for (int i = 0; i < 4; i++) {
            cp16(sa + i * (32 * 144), ga + (long long)i * 32 * lda);
            cp16(sb + i * (32 * 144), gb + (long long)i * 32 * ldb);
        }
    };

    issue(0); CP_COMMIT;
    if (nch > 1) { issue(1); CP_COMMIT; }

    const int fr = lane >> 2, fq = lane & 3;
    uint32_t af[4][4], bf[4][2];

#define LDFRAG(ks) do { \
    const int kw_ = (ks) * 8 + fq; \
    _Pragma("unroll") \
    for (int mt = 0; mt < 4; mt++) { \
        const uint32_t* p_ = Ab + (wm + mt * 16 + fr) * PITCHW + kw_; \
        af[mt][0] = p_[0]; af[mt][1] = p_[8 * PITCHW]; \
        af[mt][2] = p_[4]; af[mt][3] = p_[8 * PITCHW + 4]; \
    } \
    _Pragma("unroll") \
    for (int nt = 0; nt < 4; nt++) { \
        const uint32_t* q_ = Bb + (wn + nt * 8 + fr) * PITCHW + kw_; \
        bf[nt][0] = q_[0]; bf[nt][1] = q_[4]; \
    } \
} while (0)

#define MMASET() do { \
    _Pragma("unroll") \
    for (int mt = 0; mt < 4; mt++) \
        _Pragma("unroll") \
        for (int nt = 0; nt < 4; nt++) \
            mmaf16(acc[mt][nt], af[mt], bf[nt]); \
} while (0)

    for (int c = 0; c < nch; c++) {
        if (c + 1 < nch) { CP_WAIT1; } else { CP_WAIT0; }
        __syncthreads();
        if (c + 2 < nch) { issue(c + 2); CP_COMMIT; }

        const uint32_t* Ab = sm + (c % 3) * STAGE_W;
        const uint32_t* Bb = Ab + 128 * PITCHW;

        LDFRAG(0); MMASET();
        LDFRAG(1); MMASET();
        LDFRAG(2); MMASET();
        LDFRAG(3); MMASET();
    }
#undef LDFRAG
#undef MMASET

    // ---- epilogue ----
    const int cq = (lane & 3) * 2;
    const float* bz = bias ? (bias + (long long)blockIdx.z * bias_zs) : nullptr;
#pragma unroll
    for (int mt = 0; mt < 4; mt++) {
        int gr0 = m0 + wm + mt * 16 + fr;
        int gr1 = gr0 + 8;
#pragma unroll
        for (int nt = 0; nt < 4; nt++) {
            int gc = n0 + wn + nt * 8 + cq;
            float b0 = bz ? bz[gc] : 0.f;
            float b1 = bz ? bz[gc + 1] : 0.f;
            float v00 = acc[mt][nt][0] * alpha + b0;
            float v01 = acc[mt][nt][1] * alpha + b1;
            float v10 = acc[mt][nt][2] * alpha + b0;
            float v11 = acc[mt][nt][3] * alpha + b1;
            long long o0 = (long long)gr0 * ldc + gc;
            long long o1 = (long long)gr1 * ldc + gc;
            if (EPI == 2) {
                v00 = gelu_f(v00); v01 = gelu_f(v01);
                v10 = gelu_f(v10); v11 = gelu_f(v11);
            }
            if (EPI == 0) {
                float* C = (float*)Cg + blockIdx.z * sC;
                *(float2*)(C + o0) = make_float2(v00, v01);
                *(float2*)(C + o1) = make_float2(v10, v11);
            } else if (EPI == 1 || EPI == 2) {
                __half* C = (__half*)Cg + blockIdx.z * sC;
                *(__half2*)(C + o0) = __floats2half2_rn(v00, v01);
                *(__half2*)(C + o1) = __floats2half2_rn(v10, v11);
            } else { // EPI 4: x2 = resid + v (fp32); aux1 = f16(x2)
                float* C = (float*)Cg;
                float w00 = resid[o0] + v00, w01 = resid[o0 + 1] + v01;
                float w10 = resid[o1] + v10, w11 = resid[o1 + 1] + v11;
                *(float2*)(C + o0) = make_float2(w00, w01);
                *(float2*)(C + o1) = make_float2(w10, w11);
                *(__half2*)(aux1 + o0) = __floats2half2_rn(w00, w01);
                *(__half2*)(aux1 + o1) = __floats2half2_rn(w10, w11);
            }
        }
    }
}

static void tcg(int epi,
                const __half* A, const __half* Bm, void* C,
                int M, int N, int K, int lda, int ldb, int ldc,
                long long sA, long long sB, long long sC, int batch,
                const float* bias, int bias_zs, float alpha,
                const float* resid = nullptr, __half* aux1 = nullptr)
{
    dim3 g(N / 128, M / 128, batch), blk(256);
#define LNCH(EP) do { \
    cudaFuncSetAttribute(tc_gemm_k<EP>, cudaFuncAttributeMaxDynamicSharedMemorySize, TC_SMEM); \
    tc_gemm_k<EP><<<g, blk, TC_SMEM>>>(A, Bm, C, K, lda, ldb, ldc, sA, sB, sC, bias, bias_zs, alpha, resid, aux1); \
} while (0)
    if (epi == 0) LNCH(0);
    else if (epi == 1) LNCH(1);
    else if (epi == 2) LNCH(2);
    else LNCH(4);
#undef LNCH
}

// ================= weight transpose + f16 convert =================
__global__ void roundTh_k(const float* __restrict__ in, __half* __restrict__ out,
                          int K, int N, long long inS, long long outS)
{
    __shared__ float t[32][33];
    const float* ip = in + blockIdx.z * inS;
    __half* op = out + blockIdx.z * outS;
    int n0 = blockIdx.x * 32, k0 = blockIdx.y * 32;
    int tx = threadIdx.x & 31, ty = threadIdx.x >> 5;
#pragma unroll
    for (int i = 0; i < 32; i += 8)
        t[ty + i][tx] = ip[(long long)(k0 + ty + i) * N + n0 + tx];
    __syncthreads();
#pragma unroll
    for (int i = 0; i < 32; i += 8)
        op[(long long)(n0 + ty + i) * K + k0 + tx] = __float2half_rn(t[tx][ty + i]);
}

__global__ void cvtH_k(const float* __restrict__ a, __half* __restrict__ b, int n) {
    int i = blockIdx.x * 256 + threadIdx.x;
    if (i < n) b[i] = __float2half_rn(a[i]);
}

// memb [64][256] fp32 -> membp [128][256] f16 (zero-padded rows 64..127)
__global__ void prep_membp_k(const float* __restrict__ memb, __half* __restrict__ membp) {
    int i = blockIdx.x * 256 + threadIdx.x;   // over 128*256
    if (i >= 128 * H_) return;
    int r = i / H_;
    membp[i] = (r < M_) ? __float2half_rn(memb[i]) : __half(0.f);
}

// v transpose: qkv f16 [8 batches of S][768] cols 512.. -> vT f16 [8][H][S]
__global__ void vtrans_k(const __half* __restrict__ qkv, __half* __restrict__ vT) {
    __shared__ __half t[32][34];
    int s0 = blockIdx.x * 32, h0 = blockIdx.y * 32, z = blockIdx.z;
    int tx = threadIdx.x & 31, ty = threadIdx.x >> 5;
#pragma unroll
    for (int i = 0; i < 32; i += 8)
        t[ty + i][tx] = qkv[(long long)(z * S_ + s0 + ty + i) * 768 + 512 + h0 + tx];
    __syncthreads();
#pragma unroll
    for (int i = 0; i < 32; i += 8)
        vT[(long long)z * H_ * S_ + (long long)(h0 + ty + i) * S_ + s0 + tx] = t[tx][ty + i];
}

// pack attention outs: po [2][BS][H] f16 -> hy [BS][4H] cols [0:2H)
__global__ void pack_po_k(const __half* __restrict__ po, __half* __restrict__ hy) {
    int i = blockIdx.x * 256 + threadIdx.x;
    const int per = BS_ * H_ / 8;
    int src = i / per;
    int j = i % per;
    int t = j / (H_ / 8), h8 = j % (H_ / 8);
    uint4 v = *(const uint4*)(po + (long long)src * BS_ * H_ + (long long)t * H_ + h8 * 8);
    *(uint4*)(hy + (long long)t * 4 * H_ + src * H_ + h8 * 8) = v;
}

// MoE fuse: out = x2 + sum_e rw[t][e] * (eo[e][t][d] + be2[e][d])
__global__ void moe_fuse_k(const float* __restrict__ x2, const float* __restrict__ eo,
                           const float* __restrict__ rw, const float* __restrict__ be2,
                           float* __restrict__ out) {
    int i = blockIdx.x * 256 + threadIdx.x;
    if (i >= BS_ * D_ / 4) return;
    int t = (i * 4) / D_, d = (i * 4) % D_;
    float4 r = *(const float4*)(x2 + (long long)i * 4);
    const float* rwt = rw + (long long)t * 4;
#pragma unroll
    for (int e = 0; e < E_; e++) {
        float w = rwt[e];
        float4 v = *(const float4*)(eo + (long long)e * BS_ * D_ + (long long)t * D_ + d);
        float4 b = *(const float4*)(be2 + (long long)e * D_ + d);
        r.x += w * (v.x + b.x); r.y += w * (v.y + b.y);
        r.z += w * (v.z + b.z); r.w += w * (v.w + b.w);
    }
    *(float4*)(out + (long long)i * 4) = r;
}

// ---------------- softmax over full rows of 2048: float in, f16 probs out ----------------
__global__ void softmax2048_k(const float* __restrict__ Sc, __half* __restrict__ P) {
    __shared__ float red[256];
    const int tid = threadIdx.x;
    const float* p = Sc + (long long)blockIdx.x * 2048;
    __half* q = P + (long long)blockIdx.x * 2048;
    float v[8];
    float mx = -3.4e38f;
#pragma unroll
    for (int i = 0; i < 8; i++) { v[i] = p[tid + i * 256]; mx = fmaxf(mx, v[i]); }
    red[tid] = mx; __syncthreads();
    for (int s = 128; s; s >>= 1) { if (tid < s) red[tid] = fmaxf(red[tid], red[tid + s]); __syncthreads(); }
    mx = red[0]; __syncthreads();
    float sum = 0.f;
#pragma unroll
    for (int i = 0; i < 8; i++) { v[i] = expf(v[i] - mx); sum += v[i]; }
    red[tid] = sum; __syncthreads();
    for (int s = 128; s; s >>= 1) { if (tid < s) red[tid] += red[tid + s]; __syncthreads(); }
    float inv = 1.f / red[0];
#pragma unroll
    for (int i = 0; i < 8; i++) q[tid + i * 256] = __float2half_rn(v[i] * inv);
}

// ---------------- sparse top-k via exact radix select + masked softmax (f16 probs out) ----------------
__global__ void sparse_softmax_k(const float* __restrict__ Sc, __half* __restrict__ P) {
    __shared__ uint32_t hist[256];
    __shared__ uint32_t sfx[257];
    __shared__ uint32_t s_prefix, s_k;
    __shared__ float red[256];
    const int tid = threadIdx.x;
    const float* p = Sc + (long long)blockIdx.x * 2048;
    __half* q = P + (long long)blockIdx.x * 2048;

    float v[8]; uint32_t key[8];
    float mx = -3.4e38f;
#pragma unroll
    for (int i = 0; i < 8; i++) {
        v[i] = p[tid + i * 256];
        mx = fmaxf(mx, v[i]);
        uint32_t u = __float_as_uint(v[i]);
        key[i] = (u & 0x80000000u) ? ~u : (u | 0x80000000u);
    }
    red[tid] = mx; __syncthreads();
    for (int s = 128; s; s >>= 1) { if (tid < s) red[tid] = fmaxf(red[tid], red[tid + s]); __syncthreads(); }
    mx = red[0];

    uint32_t prefix = 0, kk = KSP_;
#pragma unroll 1
    for (int b = 3; b >= 0; b--) {
        const int sh = b * 8;
        const uint32_t pmask = (b == 3) ? 0u : ~((1u << (sh + 8)) - 1u);
        hist[tid] = 0;
        if (tid == 0) sfx[256] = 0;
        __syncthreads();
#pragma unroll
        for (int i = 0; i < 8; i++)
            if ((key[i] & pmask) == prefix)
                atomicAdd(&hist[(key[i] >> sh) & 255u], 1u);
        __syncthreads();
        sfx[tid] = hist[tid];
        __syncthreads();
        for (int off = 1; off < 256; off <<= 1) {
            uint32_t add = (tid + off < 256) ? sfx[tid + off] : 0u;
            __syncthreads();
            sfx[tid] += add;
            __syncthreads();
        }
        if (sfx[tid] >= kk && (tid == 255 || sfx[tid + 1] < kk)) {
            s_prefix = prefix | ((uint32_t)tid << sh);
            s_k = kk - sfx[tid + 1];
        }
        __syncthreads();
        prefix = s_prefix; kk = s_k;
        __syncthreads();
    }
    const uint32_t tk = prefix;
    const float thr = (tk & 0x80000000u) ? __uint_as_float(tk ^ 0x80000000u)
                                         : __uint_as_float(~tk);

    float e[8]; float sum = 0.f;
#pragma unroll
    for (int i = 0; i < 8; i++) {
        float ev = (v[i] >= thr) ? expf(v[i] - mx) : 0.f;
        e[i] = ev; sum += ev;
    }
    red[tid] = sum; __syncthreads();
    for (int s = 128; s; s >>= 1) { if (tid < s) red[tid] += red[tid + s]; __syncthreads(); }
    float inv = 1.f / red[0];
#pragma unroll
    for (int i = 0; i < 8; i++) q[tid + i * 256] = __float2half_rn(e[i] * inv);
}

// ---------------- softmax rows of 64 (reads padded fp32 [BS][128], writes f16 [BS][64]) ----------------
__global__ void softmax64_k(const float* __restrict__ mwp, __half* __restrict__ mwh, int rows) {
    int row = (blockIdx.x * blockDim.x + threadIdx.x) >> 5;
    int lane = threadIdx.x & 31;
    if (row >= rows) return;
    const float* p = mwp + (long long)row * 128;
    float a = p[lane], b = p[lane + 32];
    float mx = fmaxf(a, b);
    for (int o = 16; o; o >>= 1) mx = fmaxf(mx, __shfl_xor_sync(0xffffffffu, mx, o));
    float ea = expf(a - mx), eb = expf(b - mx);
    float s = ea + eb;
    for (int o = 16; o; o >>= 1) s += __shfl_xor_sync(0xffffffffu, s, o);
    float inv = 1.f / s;
    __half* q = mwh + (long long)row * 64;
    q[lane] = __float2half_rn(ea * inv);
    q[lane + 32] = __float2half_rn(eb * inv);
}

// ---------------- router ----------------
__global__ void router_k(const float* __restrict__ x2, const float* __restrict__ Wr,
                         const float* __restrict__ br, float* __restrict__ rw, int rows) {
    int tok = (blockIdx.x * blockDim.x + threadIdx.x) >> 5;
    int lane = threadIdx.x & 31;
    if (tok >= rows) return;
    const float* xr = x2 + (long long)tok * D_;
    float s0 = 0.f, s1 = 0.f, s2 = 0.f, s3 = 0.f;
    for (int d = lane; d < D_; d += 32) {
        float xv = xr[d];
        const float* w = Wr + d * 4;
        s0 += xv * w[0]; s1 += xv * w[1]; s2 += xv * w[2]; s3 += xv * w[3];
    }
    for (int o = 16; o; o >>= 1) {
        s0 += __shfl_xor_sync(0xffffffffu, s0, o);
        s1 += __shfl_xor_sync(0xffffffffu, s1, o);
        s2 += __shfl_xor_sync(0xffffffffu, s2, o);
        s3 += __shfl_xor_sync(0xffffffffu, s3, o);
    }
    if (lane == 0) {
        s0 += br[0]; s1 += br[1]; s2 += br[2]; s3 += br[3];
        float mx = fmaxf(fmaxf(s0, s1), fmaxf(s2, s3));
        float e0 = expf(s0 - mx), e1 = expf(s1 - mx), e2 = expf(s2 - mx), e3 = expf(s3 - mx);
        float inv = 1.f / (e0 + e1 + e2 + e3);
        float* o4 = rw + (long long)tok * 4;
        o4[0] = e0 * inv; o4[1] = e1 * inv; o4[2] = e2 * inv; o4[3] = e3 * inv;
    }
}

// ---------------- launch ----------------
extern "C" void kernel_launch(void* const* d_in, const int* in_sizes, int n_in,
                              void* d_out, int out_size) {
    const float* x     = (const float*)d_in[0];
    const float* WqkvL = (const float*)d_in[1];
    const float* WqkvS = (const float*)d_in[2];
    const float* memb  = (const float*)d_in[3];
    const float* Wm    = (const float*)d_in[4];
    const float* Wo    = (const float*)d_in[5];
    const float* bo    = (const float*)d_in[6];
    const float* Wi    = (const float*)d_in[7];
    const float* bi    = (const float*)d_in[8];
    const float* Wp1   = (const float*)d_in[9];
    const float* bp1   = (const float*)d_in[10];
    const float* Wp2   = (const float*)d_in[11];
    const float* bp2   = (const float*)d_in[12];
    const float* Wwb   = (const float*)d_in[13];
    const float* bwb   = (const float*)d_in[14];
    const float* Wr    = (const float*)d_in[15];
    const float* br    = (const float*)d_in[16];
    const float* We1   = (const float*)d_in[17];
    const float* be1   = (const float*)d_in[18];
    const float* We2   = (const float*)d_in[19];
    const float* be2   = (const float*)d_in[20];
    float* out = (float*)d_out;

    float *scf, *mwp, *x2, *rw, *eo;
    __half *xr, *qkv, *sch, *vt, *po, *hy, *mcr, *mwh, *membp, *membT, *pp, *tt, *x2r, *hh4;
    __half *wqkv, *wm, *wo, *wi, *wp1, *wp2, *wwb, *we1, *we2;
    cudaGetSymbolAddress((void**)&scf, g_scf);
    cudaGetSymbolAddress((void**)&mwp, g_mwp);
    cudaGetSymbolAddress((void**)&x2,  g_x2);
    cudaGetSymbolAddress((void**)&rw,  g_rw);
    cudaGetSymbolAddress((void**)&eo,  g_eo);
    cudaGetSymbolAddress((void**)&xr,  h_xr);
    cudaGetSymbolAddress((void**)&qkv, h_qkv);
    cudaGetSymbolAddress((void**)&sch, h_sch);
    cudaGetSymbolAddress((void**)&vt,  h_vt);
    cudaGetSymbolAddress((void**)&po,  h_po);
    cudaGetSymbolAddress((void**)&hy,  h_hy);
    cudaGetSymbolAddress((void**)&mcr, h_mcr);
    cudaGetSymbolAddress((void**)&mwh, h_mwh);
    cudaGetSymbolAddress((void**)&membp, h_membp);
    cudaGetSymbolAddress((void**)&membT, h_membT);
    cudaGetSymbolAddress((void**)&pp,  h_pp);
    cudaGetSymbolAddress((void**)&tt,  h_tt);
    cudaGetSymbolAddress((void**)&x2r, h_x2r);
    cudaGetSymbolAddress((void**)&hh4, h_hh4);
    cudaGetSymbolAddress((void**)&wqkv, h_wqkv);
    cudaGetSymbolAddress((void**)&wm,  h_wm);
    cudaGetSymbolAddress((void**)&wo,  h_wo);
    cudaGetSymbolAddress((void**)&wi,  h_wi);
    cudaGetSymbolAddress((void**)&wp1, h_wp1);
    cudaGetSymbolAddress((void**)&wp2, h_wp2);
    cudaGetSymbolAddress((void**)&wwb, h_wwb);
    cudaGetSymbolAddress((void**)&we1, h_we1);
    cudaGetSymbolAddress((void**)&we2, h_we2);

    const float scale = 0.0625f; // H^-0.5
    dim3 t256(256);

    // ---- pre-pass + attention ----
    roundTh_k<<<dim3(768 / 32, 1024 / 32, 1), t256>>>(WqkvL, wqkv, 1024, 768, 0, 0);
    roundTh_k<<<dim3(768 / 32, 1024 / 32, 1), t256>>>(WqkvS, wqkv + (size_t)768 * 1024, 1024, 768, 0, 0);
    cvtH_k<<<(BS_ * D_ + 255) / 256, 256>>>(x, xr, BS_ * D_);
    // QKV batch=2
    tcg(1, xr, wqkv, qkv, BS_, 768, D_, D_, D_, 768,
        0, (long long)768 * 1024, (long long)BS_ * 768, 2, nullptr, 0, 1.f);
    vtrans_k<<<dim3(S_ / 32, H_ / 32, 8), t256>>>(qkv, vt);
    // scores batch=8
    tcg(0, qkv, qkv + H_, scf, S_, S_, H_, 768, 768, S_,
        (long long)S_ * 768, (long long)S_ * 768, (long long)S_ * S_, 8, nullptr, 0, scale);
    softmax2048_k<<<BS_, 256>>>(scf, sch);
    sparse_softmax_k<<<BS_, 256>>>(scf + (size_t)4 * S_ * S_, sch + (size_t)4 * S_ * S_);
    // PV batch=8
    tcg(1, sch, vt, po, S_, H_, S_, S_, S_, H_,
        (long long)S_ * S_, (long long)H_ * S_, (long long)S_ * H_, 8, nullptr, 0, 1.f);
    pack_po_k<<<(2 * BS_ * H_ / 8 + 255) / 256, 256>>>(po, hy);

    // ---- memory branch (all tensor-core) ----
    roundTh_k<<<dim3(256 / 32, 1024 / 32, 1), t256>>>(Wm, wm, 1024, 256, 0, 0);
    roundTh_k<<<dim3(256 / 32, 512 / 32, 1), t256>>>(Wo, wo, 512, 256, 0, 0);
    prep_membp_k<<<(128 * H_ + 255) / 256, 256>>>(memb, membp);
    roundTh_k<<<dim3(256 / 32, 64 / 32, 1), t256>>>(memb, membT, 64, 256, 0, 0); // [64][256] -> [256][64]
    // xp f16 -> mcr[:,0:256]
    tcg(1, xr, wm, mcr, BS_, H_, D_, D_, D_, 2 * H_, 0, 0, 0, 1, nullptr, 0, 1.f);
    // mem scores: mwp[BS,128] = xp @ membp^T (padded), fp32 out
    tcg(0, mcr, membp, mwp, BS_, 128, H_, 2 * H_, H_, 128, 0, 0, 0, 1, nullptr, 0, 1.f);
    softmax64_k<<<(BS_ * 32 + 255) / 256, 256>>>(mwp, mwh, BS_);
    // retrieved f16 -> mcr[:,256:512]: mwh[BS,64] @ membT^T(=memb)
    tcg(1, mwh, membT, mcr + H_, BS_, H_, M_, M_, M_, 2 * H_, 0, 0, 0, 1, nullptr, 0, 1.f);
    tcg(1, mcr, wo, hy + 2 * H_, BS_, H_, 2 * H_, 2 * H_, 2 * H_, 4 * H_, 0, 0, 0, 1, bo, 0, 1.f);

    // ---- predictor branch ----
    roundTh_k<<<dim3(256 / 32, 1024 / 32, 1), t256>>>(Wi, wi, 1024, 256, 0, 0);
    roundTh_k<<<dim3(512 / 32, 256 / 32, 1), t256>>>(Wp1, wp1, 256, 512, 0, 0);
    roundTh_k<<<dim3(256 / 32, 512 / 32, 1), t256>>>(Wp2, wp2, 512, 256, 0, 0);
    roundTh_k<<<dim3(1024 / 32, 1024 / 32, 1), t256>>>(Wwb, wwb, 1024, 1024, 0, 0);
    tcg(1, xr, wi, pp, BS_, H_, D_, D_, D_, H_, 0, 0, 0, 1, bi, 0, 1.f);
    tcg(2, pp, wp1, tt, BS_, 2 * H_, H_, H_, H_, 2 * H_, 0, 0, 0, 1, bp1, 0, 1.f);
    tcg(1, tt, wp2, hy + 3 * H_, BS_, H_, 2 * H_, 2 * H_, 2 * H_, 4 * H_, 0, 0, 0, 1, bp2, 0, 1.f);

    // ---- hydra combine (fused: x2 = x + concat@Wwb + bwb; x2r = f16(x2)) ----
    tcg(4, hy, wwb, x2, BS_, D_, 4 * H_, 4 * H_, 4 * H_, D_, 0, 0, 0, 1, bwb, 0, 1.f, x, x2r);

    // ---- router + MoE (batched) ----
    router_k<<<(BS_ * 32 + 255) / 256, 256>>>(x2, Wr, br, rw, BS_);
    roundTh_k<<<dim3(F_ / 32, D_ / 32, E_), t256>>>(We1, we1, D_, F_, (long long)D_ * F_, (long long)F_ * D_);
    roundTh_k<<<dim3(D_ / 32, F_ / 32, E_), t256>>>(We2, we2, F_, D_, (long long)F_ * D_, (long long)D_ * F_);
    tcg(2, x2r, we1, hh4, BS_, F_, D_, D_, D_, F_,
        0, (long long)F_ * D_, (long long)BS_ * F_, 4, be1, F_, 1.f);
    tcg(0, hh4, we2, eo, BS_, D_, F_, F_, F_, D_,
        (long long)BS_ * F_, (long long)D_ * F_, (long long)BS_ * D_, 4, nullptr, 0, 1.f);
    moe_fuse_k<<<(BS_ * D_ / 4 + 255) / 256, 256>>>(x2, eo, rw, be2, out);
}